// round 1
// baseline (speedup 1.0000x reference)
#include <cuda_runtime.h>
#include <cstdint>

#define N_NODES 4096
#define EMB     512
#define N_HEADS 8
#define KSP     128
#define HD      64

// Scratch for projected Q and K, natural [N, D] layout (head h slice = cols h*64..h*64+63)
__device__ float g_Q[N_NODES * EMB];
__device__ float g_K[N_NODES * EMB];

// ---------------------------------------------------------------------------
// Projection GEMM: C[n,j] = sum_d X[n,d] * W[j,d] + b[j]   (torch Linear: x @ W.T + b)
// blockIdx.z = 0 -> (Wq,bq)->g_Q ; 1 -> (Wk,bk)->g_K
// Tiles: BM=128, BN=64, BK=16; 256 threads; per-thread 8x4 register tile.
// ---------------------------------------------------------------------------
#define BM 128
#define BN 64
#define BK 16
#define TM 8
#define TN 4

__global__ void __launch_bounds__(256)
proj_gemm_kernel(const float* __restrict__ X,
                 const float* __restrict__ Wq, const float* __restrict__ bq,
                 const float* __restrict__ Wk, const float* __restrict__ bk)
{
    const float* W    = blockIdx.z ? Wk : Wq;
    const float* bias = blockIdx.z ? bk : bq;
    float*       C    = blockIdx.z ? g_K : g_Q;

    __shared__ float Xs[BK][BM + 4];   // +4 pad: keeps 16B alignment, kills STS conflicts
    __shared__ float Ws[BK][BN + 4];

    const int t  = threadIdx.x;
    const int tx = t & 15;        // N direction (TN=4)
    const int ty = t >> 4;        // M direction (TM=8)
    const int rowBase = blockIdx.y * BM;
    const int colBase = blockIdx.x * BN;

    float acc[TM][TN];
    #pragma unroll
    for (int i = 0; i < TM; i++)
        #pragma unroll
        for (int j = 0; j < TN; j++) acc[i][j] = 0.0f;

    for (int k0 = 0; k0 < EMB; k0 += BK) {
        // Load X tile (128 rows x 16 k) transposed into Xs[k][m]
        #pragma unroll
        for (int r = 0; r < 2; r++) {
            int m  = (t >> 2) + r * 64;
            int d4 = (t & 3) * 4;
            float4 v = *(const float4*)(X + (size_t)(rowBase + m) * EMB + k0 + d4);
            Xs[d4 + 0][m] = v.x; Xs[d4 + 1][m] = v.y;
            Xs[d4 + 2][m] = v.z; Xs[d4 + 3][m] = v.w;
        }
        // Load W tile (64 rows x 16 k) transposed into Ws[k][j]
        {
            int j  = t >> 2;
            int d4 = (t & 3) * 4;
            float4 v = *(const float4*)(W + (size_t)(colBase + j) * EMB + k0 + d4);
            Ws[d4 + 0][j] = v.x; Ws[d4 + 1][j] = v.y;
            Ws[d4 + 2][j] = v.z; Ws[d4 + 3][j] = v.w;
        }
        __syncthreads();

        #pragma unroll
        for (int dd = 0; dd < BK; dd++) {
            float4 a0 = *(const float4*)&Xs[dd][ty * TM];
            float4 a1 = *(const float4*)&Xs[dd][ty * TM + 4];
            float4 bv = *(const float4*)&Ws[dd][tx * TN];
            float a[TM] = {a0.x, a0.y, a0.z, a0.w, a1.x, a1.y, a1.z, a1.w};
            float b4[TN] = {bv.x, bv.y, bv.z, bv.w};
            #pragma unroll
            for (int i = 0; i < TM; i++)
                #pragma unroll
                for (int j = 0; j < TN; j++)
                    acc[i][j] = fmaf(a[i], b4[j], acc[i][j]);
        }
        __syncthreads();
    }

    float4 bb = *(const float4*)(bias + colBase + tx * TN);
    #pragma unroll
    for (int i = 0; i < TM; i++) {
        float4 o;
        o.x = acc[i][0] + bb.x;
        o.y = acc[i][1] + bb.y;
        o.z = acc[i][2] + bb.z;
        o.w = acc[i][3] + bb.w;
        *(float4*)(C + (size_t)(rowBase + ty * TM + i) * EMB + colBase + tx * TN) = o;
    }
}

// ---------------------------------------------------------------------------
// Score + scatter + row streamout.
// One CTA per (h, n): b = h*4096 + n. Assemble the 4096-float output row in
// SMEM (zero, scatter 128 scores), then stream it out coalesced.
// Dot products: half-warp (16 lanes) per key, float4 per lane (64 values).
// ---------------------------------------------------------------------------
__global__ void __launch_bounds__(256)
scatter_scores_kernel(const int* __restrict__ sidx, float* __restrict__ out)
{
    __shared__ float row[N_NODES];
    __shared__ float qs[HD];

    const int b = blockIdx.x;
    const int n = b & (N_NODES - 1);
    const int h = b >> 12;
    const int t = threadIdx.x;

    // Stage the query vector (64 floats)
    if (t < 16)
        ((float4*)qs)[t] = ((const float4*)(g_Q + (size_t)n * EMB + h * HD))[t];

    // Zero the output row (4096 floats = 1024 float4)
    float4 z = make_float4(0.f, 0.f, 0.f, 0.f);
    #pragma unroll
    for (int i = 0; i < 4; i++) ((float4*)row)[t + i * 256] = z;
    __syncthreads();

    const int warp = t >> 5;
    const int lane = t & 31;
    const int half = lane >> 4;   // 0 or 1: which key of the pair
    const int hl   = lane & 15;   // lane within half-warp

    // This warp handles keys [warp*16, warp*16+16). Preload indices (16 distinct).
    const int base = (((h << 12) | n) * KSP) + warp * 16;
    int idxreg = sidx[base + hl];           // lanes 0-15 & 16-31 hold the same 16 idx

    float4 qv = ((const float4*)qs)[hl];

    #pragma unroll
    for (int j = 0; j < 8; j++) {
        int kidx = __shfl_sync(0xffffffffu, idxreg, 2 * j + half);
        float4 kv = ((const float4*)(g_K + (size_t)kidx * EMB + h * HD))[hl];
        float s = qv.x * kv.x + qv.y * kv.y + qv.z * kv.z + qv.w * kv.w;
        // reduce within 16-lane group (xor masks stay inside the half-warp)
        s += __shfl_xor_sync(0xffffffffu, s, 8);
        s += __shfl_xor_sync(0xffffffffu, s, 4);
        s += __shfl_xor_sync(0xffffffffu, s, 2);
        s += __shfl_xor_sync(0xffffffffu, s, 1);
        // Duplicate idx across warps/halves compute identical values -> benign race
        if (hl == 0) row[kidx] = s * 0.125f;   // 1/sqrt(64)
    }
    __syncthreads();

    // Coalesced streamout of the full row
    float4* op = (float4*)(out + (size_t)b * N_NODES);
    #pragma unroll
    for (int i = 0; i < 4; i++) op[t + i * 256] = ((float4*)row)[t + i * 256];
}

// ---------------------------------------------------------------------------
extern "C" void kernel_launch(void* const* d_in, const int* in_sizes, int n_in,
                              void* d_out, int out_size)
{
    const float* emb = (const float*)d_in[0];
    const float* Wq  = (const float*)d_in[1];
    const float* bq  = (const float*)d_in[2];
    const float* Wk  = (const float*)d_in[3];
    const float* bk  = (const float*)d_in[4];
    const int*   idx = (const int*)d_in[5];
    float* out = (float*)d_out;

    dim3 ggrid(EMB / BN, N_NODES / BM, 2);   // 8 x 32 x 2
    proj_gemm_kernel<<<ggrid, 256>>>(emb, Wq, bq, Wk, bk);

    scatter_scores_kernel<<<N_HEADS * N_NODES, 256>>>(idx, out);
}

// round 2
// speedup vs baseline: 1.1045x; 1.1045x over previous
#include <cuda_runtime.h>
#include <cstdint>

#define N_NODES 4096
#define EMB     512
#define N_HEADS 8
#define KSP     128
#define HD      64

// Scratch for projected Q and K, natural [N, D] layout (head h slice = cols h*64..h*64+63)
__device__ float g_Q[N_NODES * EMB];
__device__ float g_K[N_NODES * EMB];

// ---------------------------------------------------------------------------
// Projection GEMM: C[n,j] = sum_d X[n,d] * W[j,d] + b[j]   (torch Linear: x @ W.T + b)
// blockIdx.z = 0 -> (Wq,bq)->g_Q ; 1 -> (Wk,bk)->g_K
// Tiles: BM=128, BN=64, BK=16; 256 threads; per-thread 8x4 register tile.
// At the fp32 FMA roofline (~114us) — left unchanged this round.
// ---------------------------------------------------------------------------
#define BM 128
#define BN 64
#define BK 16
#define TM 8
#define TN 4

__global__ void __launch_bounds__(256)
proj_gemm_kernel(const float* __restrict__ X,
                 const float* __restrict__ Wq, const float* __restrict__ bq,
                 const float* __restrict__ Wk, const float* __restrict__ bk)
{
    const float* W    = blockIdx.z ? Wk : Wq;
    const float* bias = blockIdx.z ? bk : bq;
    float*       C    = blockIdx.z ? g_K : g_Q;

    __shared__ float Xs[BK][BM + 4];
    __shared__ float Ws[BK][BN + 4];

    const int t  = threadIdx.x;
    const int tx = t & 15;        // N direction (TN=4)
    const int ty = t >> 4;        // M direction (TM=8)
    const int rowBase = blockIdx.y * BM;
    const int colBase = blockIdx.x * BN;

    float acc[TM][TN];
    #pragma unroll
    for (int i = 0; i < TM; i++)
        #pragma unroll
        for (int j = 0; j < TN; j++) acc[i][j] = 0.0f;

    for (int k0 = 0; k0 < EMB; k0 += BK) {
        #pragma unroll
        for (int r = 0; r < 2; r++) {
            int m  = (t >> 2) + r * 64;
            int d4 = (t & 3) * 4;
            float4 v = *(const float4*)(X + (size_t)(rowBase + m) * EMB + k0 + d4);
            Xs[d4 + 0][m] = v.x; Xs[d4 + 1][m] = v.y;
            Xs[d4 + 2][m] = v.z; Xs[d4 + 3][m] = v.w;
        }
        {
            int j  = t >> 2;
            int d4 = (t & 3) * 4;
            float4 v = *(const float4*)(W + (size_t)(colBase + j) * EMB + k0 + d4);
            Ws[d4 + 0][j] = v.x; Ws[d4 + 1][j] = v.y;
            Ws[d4 + 2][j] = v.z; Ws[d4 + 3][j] = v.w;
        }
        __syncthreads();

        #pragma unroll
        for (int dd = 0; dd < BK; dd++) {
            float4 a0 = *(const float4*)&Xs[dd][ty * TM];
            float4 a1 = *(const float4*)&Xs[dd][ty * TM + 4];
            float4 bv = *(const float4*)&Ws[dd][tx * TN];
            float a[TM] = {a0.x, a0.y, a0.z, a0.w, a1.x, a1.y, a1.z, a1.w};
            float b4[TN] = {bv.x, bv.y, bv.z, bv.w};
            #pragma unroll
            for (int i = 0; i < TM; i++)
                #pragma unroll
                for (int j = 0; j < TN; j++)
                    acc[i][j] = fmaf(a[i], b4[j], acc[i][j]);
        }
        __syncthreads();
    }

    float4 bb = *(const float4*)(bias + colBase + tx * TN);
    #pragma unroll
    for (int i = 0; i < TM; i++) {
        float4 o;
        o.x = acc[i][0] + bb.x;
        o.y = acc[i][1] + bb.y;
        o.z = acc[i][2] + bb.z;
        o.w = acc[i][3] + bb.w;
        *(float4*)(C + (size_t)(rowBase + ty * TM + i) * EMB + colBase + tx * TN) = o;
    }
}

// ---------------------------------------------------------------------------
// Score + scatter, v2: NO SMEM row staging.
// One CTA per (h, n). Zero-fill the 16KB output row directly in GMEM
// (coalesced float4), __syncthreads (CTA-scope fence, covers global), then
// scatter the 128 scores as direct 4B STGs. The scattered stores hit L2
// lines just written by the zero-fill (still resident), so DRAM write
// traffic stays ~512MB total.
// Gather: half-warp (16 lanes) per key, float4/lane; loads batched 4-deep
// for MLP to cover L2 latency. Duplicate indices produce identical scores
// -> any write order is correct (matches last-write-wins).
// ---------------------------------------------------------------------------
__global__ void __launch_bounds__(256)
scatter_scores_kernel(const int* __restrict__ sidx, float* __restrict__ out)
{
    const int b = blockIdx.x;
    const int n = b & (N_NODES - 1);
    const int h = b >> 12;
    const int t = threadIdx.x;

    float* rowp = out + (size_t)b * N_NODES;

    // Zero-fill the output row directly: 1024 float4 across 256 threads.
    float4 z = make_float4(0.f, 0.f, 0.f, 0.f);
    float4* op = (float4*)rowp;
    #pragma unroll
    for (int i = 0; i < 4; i++) op[t + i * 256] = z;

    const int warp = t >> 5;
    const int lane = t & 31;
    const int half = lane >> 4;   // which key of the pair handled by this warp-half
    const int hl   = lane & 15;   // lane within half-warp (16B slice of the 256B row)

    // Warp handles keys [warp*16, warp*16+16). Lanes 0-15 and 16-31 load the
    // same 16 indices (hl repeats), so shuffles below stay uniform.
    const int base = (((h << 12) | n) * KSP) + warp * 16;
    int idxreg = sidx[base + hl];

    // Query slice: all warps read the same 256B -> L1-broadcast, no SMEM needed.
    float4 qv = ((const float4*)(g_Q + (size_t)n * EMB + h * HD))[hl];

    __syncthreads();   // zero-fill visible before scattered overwrites

    #pragma unroll
    for (int batch = 0; batch < 2; batch++) {
        int    kidx[4];
        float4 kv[4];
        // Issue all 4 gather loads before consuming -> MLP=4 per warp
        #pragma unroll
        for (int j = 0; j < 4; j++) {
            kidx[j] = __shfl_sync(0xffffffffu, idxreg, 2 * (batch * 4 + j) + half);
            kv[j]   = ((const float4*)(g_K + (size_t)kidx[j] * EMB + h * HD))[hl];
        }
        #pragma unroll
        for (int j = 0; j < 4; j++) {
            float s = qv.x * kv[j].x + qv.y * kv[j].y + qv.z * kv[j].z + qv.w * kv[j].w;
            s += __shfl_xor_sync(0xffffffffu, s, 8);
            s += __shfl_xor_sync(0xffffffffu, s, 4);
            s += __shfl_xor_sync(0xffffffffu, s, 2);
            s += __shfl_xor_sync(0xffffffffu, s, 1);
            if (hl == 0) rowp[kidx[j]] = s * 0.125f;   // 1/sqrt(64)
        }
    }
}

// ---------------------------------------------------------------------------
extern "C" void kernel_launch(void* const* d_in, const int* in_sizes, int n_in,
                              void* d_out, int out_size)
{
    const float* emb = (const float*)d_in[0];
    const float* Wq  = (const float*)d_in[1];
    const float* bq  = (const float*)d_in[2];
    const float* Wk  = (const float*)d_in[3];
    const float* bk  = (const float*)d_in[4];
    const int*   idx = (const int*)d_in[5];
    float* out = (float*)d_out;

    dim3 ggrid(EMB / BN, N_NODES / BM, 2);   // 8 x 32 x 2
    proj_gemm_kernel<<<ggrid, 256>>>(emb, Wq, bq, Wk, bk);

    scatter_scores_kernel<<<N_HEADS * N_NODES, 256>>>(idx, out);
}

// round 3
// speedup vs baseline: 1.2195x; 1.1041x over previous
#include <cuda_runtime.h>
#include <cuda_fp16.h>
#include <cstdint>

#define N_NODES 4096
#define EMB     512
#define N_HEADS 8
#define KSP     128
#define HD      64

// Projected Q (fp32) and K (fp16). K row = 1KB; head slice = 128B, line-aligned.
__device__ float  g_Q [N_NODES * EMB];
__device__ __half g_Kh[N_NODES * EMB];

// ---------------------------------------------------------------------------
// Projection GEMM: C[n,j] = sum_d X[n,d] * W[j,d] + b[j]
// blockIdx.z = 0 -> (Wq,bq)->g_Q (fp32) ; 1 -> (Wk,bk)->g_Kh (fp16)
// fp32 accumulate throughout; only K's output store rounds to fp16.
// ---------------------------------------------------------------------------
#define BM 128
#define BN 64
#define BK 16
#define TM 8
#define TN 4

__global__ void __launch_bounds__(256)
proj_gemm_kernel(const float* __restrict__ X,
                 const float* __restrict__ Wq, const float* __restrict__ bq,
                 const float* __restrict__ Wk, const float* __restrict__ bk)
{
    const float* W    = blockIdx.z ? Wk : Wq;
    const float* bias = blockIdx.z ? bk : bq;

    __shared__ float Xs[BK][BM + 4];
    __shared__ float Ws[BK][BN + 4];

    const int t  = threadIdx.x;
    const int tx = t & 15;        // N direction (TN=4)
    const int ty = t >> 4;        // M direction (TM=8)
    const int rowBase = blockIdx.y * BM;
    const int colBase = blockIdx.x * BN;

    float acc[TM][TN];
    #pragma unroll
    for (int i = 0; i < TM; i++)
        #pragma unroll
        for (int j = 0; j < TN; j++) acc[i][j] = 0.0f;

    for (int k0 = 0; k0 < EMB; k0 += BK) {
        #pragma unroll
        for (int r = 0; r < 2; r++) {
            int m  = (t >> 2) + r * 64;
            int d4 = (t & 3) * 4;
            float4 v = *(const float4*)(X + (size_t)(rowBase + m) * EMB + k0 + d4);
            Xs[d4 + 0][m] = v.x; Xs[d4 + 1][m] = v.y;
            Xs[d4 + 2][m] = v.z; Xs[d4 + 3][m] = v.w;
        }
        {
            int j  = t >> 2;
            int d4 = (t & 3) * 4;
            float4 v = *(const float4*)(W + (size_t)(colBase + j) * EMB + k0 + d4);
            Ws[d4 + 0][j] = v.x; Ws[d4 + 1][j] = v.y;
            Ws[d4 + 2][j] = v.z; Ws[d4 + 3][j] = v.w;
        }
        __syncthreads();

        #pragma unroll
        for (int dd = 0; dd < BK; dd++) {
            float4 a0 = *(const float4*)&Xs[dd][ty * TM];
            float4 a1 = *(const float4*)&Xs[dd][ty * TM + 4];
            float4 bv = *(const float4*)&Ws[dd][tx * TN];
            float a[TM] = {a0.x, a0.y, a0.z, a0.w, a1.x, a1.y, a1.z, a1.w};
            float b4[TN] = {bv.x, bv.y, bv.z, bv.w};
            #pragma unroll
            for (int i = 0; i < TM; i++)
                #pragma unroll
                for (int j = 0; j < TN; j++)
                    acc[i][j] = fmaf(a[i], b4[j], acc[i][j]);
        }
        __syncthreads();
    }

    float4 bb = *(const float4*)(bias + colBase + tx * TN);
    if (blockIdx.z == 0) {
        #pragma unroll
        for (int i = 0; i < TM; i++) {
            float4 o;
            o.x = acc[i][0] + bb.x;
            o.y = acc[i][1] + bb.y;
            o.z = acc[i][2] + bb.z;
            o.w = acc[i][3] + bb.w;
            *(float4*)(g_Q + (size_t)(rowBase + ty * TM + i) * EMB + colBase + tx * TN) = o;
        }
    } else {
        #pragma unroll
        for (int i = 0; i < TM; i++) {
            __half2 h0 = __floats2half2_rn(acc[i][0] + bb.x, acc[i][1] + bb.y);
            __half2 h1 = __floats2half2_rn(acc[i][2] + bb.z, acc[i][3] + bb.w);
            uint2 o;
            o.x = *(unsigned*)&h0;
            o.y = *(unsigned*)&h1;
            *(uint2*)(g_Kh + (size_t)(rowBase + ty * TM + i) * EMB + colBase + tx * TN) = o;
        }
    }
}

// ---------------------------------------------------------------------------
// Score + scatter, v3: fp16 key gather (one 128B line per key).
// One CTA per (h, n). Zero-fill the row directly in GMEM, then scatter.
// Gather: 8 lanes x 16B per key -> one warp LDG.128 covers 4 keys; all 4
// warp-loads issued up-front (MLP=4). Reduction over the 8-lane group.
// Duplicate indices -> identical scores -> benign race.
// ---------------------------------------------------------------------------
__global__ void __launch_bounds__(256)
scatter_scores_kernel(const int* __restrict__ sidx, float* __restrict__ out)
{
    const int b = blockIdx.x;
    const int n = b & (N_NODES - 1);
    const int h = b >> 12;
    const int t = threadIdx.x;

    float* rowp = out + (size_t)b * N_NODES;

    // Zero-fill the output row: 1024 float4 across 256 threads.
    float4 z = make_float4(0.f, 0.f, 0.f, 0.f);
    float4* op = (float4*)rowp;
    #pragma unroll
    for (int i = 0; i < 4; i++) op[t + i * 256] = z;

    const int warp = t >> 5;
    const int lane = t & 31;
    const int quad = lane >> 3;   // which key within the group of 4
    const int sub  = lane & 7;    // 16B slice (8 halfs) within the 128B key row

    // Warp handles keys [warp*16, warp*16+16). Lanes 0-15/16-31 mirror the idx.
    const int base = (((h << 12) | n) * KSP) + warp * 16;
    int idxreg = sidx[base + (lane & 15)];

    // Query slice: floats [sub*8, sub*8+8) — L1-broadcast across warps.
    const float4* qp = (const float4*)(g_Q + (size_t)n * EMB + h * HD);
    float4 qa = qp[sub * 2];
    float4 qb = qp[sub * 2 + 1];

    __syncthreads();   // zero-fill visible before scattered overwrites

    int  kidx[4];
    uint4 kv[4];
    #pragma unroll
    for (int j = 0; j < 4; j++) {
        kidx[j] = __shfl_sync(0xffffffffu, idxreg, 4 * j + quad);
        kv[j] = *(const uint4*)(g_Kh + (size_t)kidx[j] * EMB + h * HD + sub * 8);
    }

    #pragma unroll
    for (int j = 0; j < 4; j++) {
        float2 f0 = __half22float2(*(const __half2*)&kv[j].x);
        float2 f1 = __half22float2(*(const __half2*)&kv[j].y);
        float2 f2 = __half22float2(*(const __half2*)&kv[j].z);
        float2 f3 = __half22float2(*(const __half2*)&kv[j].w);
        float s;
        s  = qa.x * f0.x + qa.y * f0.y;
        s += qa.z * f1.x + qa.w * f1.y;
        s += qb.x * f2.x + qb.y * f2.y;
        s += qb.z * f3.x + qb.w * f3.y;
        // reduce across the 8-lane group
        s += __shfl_xor_sync(0xffffffffu, s, 4);
        s += __shfl_xor_sync(0xffffffffu, s, 2);
        s += __shfl_xor_sync(0xffffffffu, s, 1);
        if (sub == 0) rowp[kidx[j]] = s * 0.125f;   // 1/sqrt(64)
    }
}

// ---------------------------------------------------------------------------
extern "C" void kernel_launch(void* const* d_in, const int* in_sizes, int n_in,
                              void* d_out, int out_size)
{
    const float* emb = (const float*)d_in[0];
    const float* Wq  = (const float*)d_in[1];
    const float* bq  = (const float*)d_in[2];
    const float* Wk  = (const float*)d_in[3];
    const float* bk  = (const float*)d_in[4];
    const int*   idx = (const int*)d_in[5];
    float* out = (float*)d_out;

    dim3 ggrid(EMB / BN, N_NODES / BM, 2);   // 8 x 32 x 2
    proj_gemm_kernel<<<ggrid, 256>>>(emb, Wq, bq, Wk, bk);

    scatter_scores_kernel<<<N_HEADS * N_NODES, 256>>>(idx, out);
}

// round 6
// speedup vs baseline: 1.4198x; 1.1642x over previous
#include <cuda_runtime.h>
#include <cuda_fp16.h>
#include <cuda_bf16.h>
#include <cstdint>

#define N_NODES 4096
#define EMB     512
#define N_HEADS 8
#define KSP     128
#define HD      64
#define K_TOT   1536          // 3 * EMB (bf16 split: [hi|lo|hi] x [hi|hi|lo])

// Projected Q (fp32) and K (fp16). K row = 1KB; head slice = 128B, line-aligned.
__device__ float  g_Q [N_NODES * EMB];
__device__ __half g_Kh[N_NODES * EMB];

// bf16-split operands for the projection GEMMs
__device__ __align__(16) __nv_bfloat16 g_X2 [N_NODES * K_TOT];   // [hi | lo | hi]
__device__ __align__(16) __nv_bfloat16 g_W2q[EMB * K_TOT];       // [hi | hi | lo]
__device__ __align__(16) __nv_bfloat16 g_W2k[EMB * K_TOT];

// ════════════════ portable PTX helpers (valid at compute_103) ═══════════════
__device__ __forceinline__ uint32_t smem_u32_of(const void* p) {
    uint32_t a;
    asm("{ .reg .u64 t; cvta.to.shared.u64 t, %1; cvt.u32.u64 %0, t; }" : "=r"(a) : "l"(p));
    return a;
}
__device__ __forceinline__ void ldsm_x4(uint32_t* r, uint32_t addr) {
    asm volatile("ldmatrix.sync.aligned.m8n8.x4.shared.b16 {%0,%1,%2,%3}, [%4];"
                 : "=r"(r[0]), "=r"(r[1]), "=r"(r[2]), "=r"(r[3]) : "r"(addr));
}
__device__ __forceinline__ void mma_bf16(float* c, const uint32_t* a, const uint32_t* b) {
    asm volatile(
        "mma.sync.aligned.m16n8k16.row.col.f32.bf16.bf16.f32 "
        "{%0,%1,%2,%3}, {%4,%5,%6,%7}, {%8,%9}, {%0,%1,%2,%3};"
        : "+f"(c[0]), "+f"(c[1]), "+f"(c[2]), "+f"(c[3])
        : "r"(a[0]), "r"(a[1]), "r"(a[2]), "r"(a[3]), "r"(b[0]), "r"(b[1]));
}

// ---------------------------------------------------------------------------
// bf16 split conversion. One block per source row (512 floats).
// mode 0 (activations): segs [hi | lo | hi]; mode 1 (weights): [hi | hi | lo]
// ---------------------------------------------------------------------------
__global__ void __launch_bounds__(256)
split_convert_kernel(const float* __restrict__ src, __nv_bfloat16* __restrict__ dst, int mode)
{
    const int row = blockIdx.x;
    const int c   = threadIdx.x * 2;
    float2 v = *(const float2*)(src + (size_t)row * EMB + c);
    __nv_bfloat16 h0 = __float2bfloat16_rn(v.x);
    __nv_bfloat16 h1 = __float2bfloat16_rn(v.y);
    __nv_bfloat16 l0 = __float2bfloat16_rn(v.x - __bfloat162float(h0));
    __nv_bfloat16 l1 = __float2bfloat16_rn(v.y - __bfloat162float(h1));
    __nv_bfloat162 H = {h0, h1}, L = {l0, l1};
    __nv_bfloat162* d0 = (__nv_bfloat162*)(dst + (size_t)row * K_TOT + c);
    d0[0] = H;
    if (mode == 0) { d0[256] = L; d0[512] = H; }
    else           { d0[256] = H; d0[512] = L; }
}

// ---------------------------------------------------------------------------
// HMMA projection GEMM: C[4096,512] = X2[4096,1536] @ W2^T (both K-major bf16),
// fp32 accumulate. grid=(512/64, 4096/128, 2); z=0 -> g_Q(+bq), z=1 -> g_Kh(+bk).
// CTA 128x64, BK=32, 8 warps in 4x2, warp tile 32x32 (2 m16 x 4 n8 frags).
// Double-buffered SMEM, rows padded to 40 halves (conflict-free ldmatrix).
// B loaded with NON-transposed ldmatrix: Bs[n][k] row-major IS the col-major
// k x n operand mma.row.col expects; thread t then holds B^T[n=t/4][k=2(t%4)]
// = the exact b-fragment. (Round-5 bug: trans variant transposed each atom.)
// ---------------------------------------------------------------------------
#define BKG   32
#define NITER (K_TOT / BKG)     // 48
#define APAD  40                // 32 + 8 halves -> 80B row stride

__global__ void __launch_bounds__(256)
proj_mma_kernel(const float* __restrict__ bq, const float* __restrict__ bk)
{
    __shared__ __align__(16) __nv_bfloat16 As[2][128][APAD];
    __shared__ __align__(16) __nv_bfloat16 Bs[2][64][APAD];

    const int t      = threadIdx.x;
    const int wid    = t >> 5;
    const int lane   = t & 31;
    const int warp_m = wid & 3;   // 4 warps over M (32 rows each)
    const int warp_n = wid >> 2;  // 2 warps over N (32 cols each)
    const int z      = blockIdx.z;
    const int rowBase = blockIdx.y * 128;
    const int colBase = blockIdx.x * 64;

    const __nv_bfloat16* Asrc = g_X2 + (size_t)rowBase * K_TOT;
    const __nv_bfloat16* Bsrc = (z ? g_W2k : g_W2q) + (size_t)colBase * K_TOT;

    // gmem->smem chunk mapping (uint4 = 8 halves)
    const int ar0 = (t + 0)   >> 2, ac0 = (t + 0)   & 3;   // A chunk 0
    const int ar1 = (t + 256) >> 2, ac1 = (t + 256) & 3;   // A chunk 1
    const int br  = t >> 2,         bc  = t & 3;           // B chunk

    float acc[2][4][4];
    #pragma unroll
    for (int mi = 0; mi < 2; mi++)
        #pragma unroll
        for (int ni = 0; ni < 4; ni++)
            #pragma unroll
            for (int e = 0; e < 4; e++) acc[mi][ni][e] = 0.0f;

    // ldmatrix base addresses for both buffers
    const int arow = warp_m * 32 + (lane & 15);
    const int acol = (lane >> 4) * 8;
    const int brow = warp_n * 32 + (lane & 15);
    uint32_t aAddr[2] = { smem_u32_of(&As[0][arow][acol]), smem_u32_of(&As[1][arow][acol]) };
    uint32_t bAddr[2] = { smem_u32_of(&Bs[0][brow][acol]), smem_u32_of(&Bs[1][brow][acol]) };

    // preload iter 0
    *(uint4*)&As[0][ar0][ac0 * 8] = *(const uint4*)(Asrc + (size_t)ar0 * K_TOT + ac0 * 8);
    *(uint4*)&As[0][ar1][ac1 * 8] = *(const uint4*)(Asrc + (size_t)ar1 * K_TOT + ac1 * 8);
    *(uint4*)&Bs[0][br][bc * 8]   = *(const uint4*)(Bsrc + (size_t)br  * K_TOT + bc  * 8);
    __syncthreads();

    #pragma unroll 1
    for (int it = 0; it < NITER; ++it) {
        const int b  = it & 1;
        const bool pf = (it + 1 < NITER);
        uint4 ra0, ra1, rb;
        if (pf) {
            const int k1 = (it + 1) * BKG;
            ra0 = *(const uint4*)(Asrc + (size_t)ar0 * K_TOT + k1 + ac0 * 8);
            ra1 = *(const uint4*)(Asrc + (size_t)ar1 * K_TOT + k1 + ac1 * 8);
            rb  = *(const uint4*)(Bsrc + (size_t)br  * K_TOT + k1 + bc  * 8);
        }

        #pragma unroll
        for (int ks = 0; ks < 2; ks++) {
            uint32_t a[2][4];
            ldsm_x4(a[0], aAddr[b] + ks * 32);                   // m tile 0
            ldsm_x4(a[1], aAddr[b] + 16 * (APAD * 2) + ks * 32); // m tile 1 (+16 rows)
            // B: non-trans x4. r0 = n0-7/k0-7 (b0 of ni even), r1 = n8-15/k0-7,
            // r2 = n0-7/k8-15 (b1 of ni even), r3 = n8-15/k8-15.
            uint32_t bf[4][2];
            {
                uint32_t r[4];
                ldsm_x4(r, bAddr[b] + ks * 32);
                bf[0][0] = r[0]; bf[0][1] = r[2];
                bf[1][0] = r[1]; bf[1][1] = r[3];
                ldsm_x4(r, bAddr[b] + 16 * (APAD * 2) + ks * 32);
                bf[2][0] = r[0]; bf[2][1] = r[2];
                bf[3][0] = r[1]; bf[3][1] = r[3];
            }
            #pragma unroll
            for (int mi = 0; mi < 2; mi++)
                #pragma unroll
                for (int ni = 0; ni < 4; ni++)
                    mma_bf16(acc[mi][ni], a[mi], bf[ni]);
        }

        if (pf) {
            const int nb = 1 - b;
            *(uint4*)&As[nb][ar0][ac0 * 8] = ra0;
            *(uint4*)&As[nb][ar1][ac1 * 8] = ra1;
            *(uint4*)&Bs[nb][br][bc * 8]   = rb;
            __syncthreads();
        }
    }

    // Epilogue: d-frag m16n8 -> rows lane/4 (+8), cols (lane&3)*2.. ; add bias.
    const float* bias = z ? bk : bq;
    const int mrow = rowBase + warp_m * 32 + (lane >> 2);
    #pragma unroll
    for (int mi = 0; mi < 2; mi++) {
        #pragma unroll
        for (int ni = 0; ni < 4; ni++) {
            const int gn = colBase + warp_n * 32 + ni * 8 + (lane & 3) * 2;
            const float2 bb = *(const float2*)(bias + gn);
            const int gm0 = mrow + mi * 16;
            if (z == 0) {
                float2 o0 = { acc[mi][ni][0] + bb.x, acc[mi][ni][1] + bb.y };
                float2 o1 = { acc[mi][ni][2] + bb.x, acc[mi][ni][3] + bb.y };
                *(float2*)(g_Q + (size_t)gm0 * EMB + gn)       = o0;
                *(float2*)(g_Q + (size_t)(gm0 + 8) * EMB + gn) = o1;
            } else {
                __half2 o0 = __floats2half2_rn(acc[mi][ni][0] + bb.x, acc[mi][ni][1] + bb.y);
                __half2 o1 = __floats2half2_rn(acc[mi][ni][2] + bb.x, acc[mi][ni][3] + bb.y);
                *(__half2*)(g_Kh + (size_t)gm0 * EMB + gn)       = o0;
                *(__half2*)(g_Kh + (size_t)(gm0 + 8) * EMB + gn) = o1;
            }
        }
    }
}

// ---------------------------------------------------------------------------
// Score + scatter (unchanged, 101.5us verified): fp16 key gather, one 128B
// line per key, direct GMEM zero-fill + scattered 4B stores.
// ---------------------------------------------------------------------------
__global__ void __launch_bounds__(256)
scatter_scores_kernel(const int* __restrict__ sidx, float* __restrict__ out)
{
    const int b = blockIdx.x;
    const int n = b & (N_NODES - 1);
    const int h = b >> 12;
    const int t = threadIdx.x;

    float* rowp = out + (size_t)b * N_NODES;

    float4 z = make_float4(0.f, 0.f, 0.f, 0.f);
    float4* op = (float4*)rowp;
    #pragma unroll
    for (int i = 0; i < 4; i++) op[t + i * 256] = z;

    const int warp = t >> 5;
    const int lane = t & 31;
    const int quad = lane >> 3;
    const int sub  = lane & 7;

    const int base = (((h << 12) | n) * KSP) + warp * 16;
    int idxreg = sidx[base + (lane & 15)];

    const float4* qp = (const float4*)(g_Q + (size_t)n * EMB + h * HD);
    float4 qa = qp[sub * 2];
    float4 qb = qp[sub * 2 + 1];

    __syncthreads();

    int  kidx[4];
    uint4 kv[4];
    #pragma unroll
    for (int j = 0; j < 4; j++) {
        kidx[j] = __shfl_sync(0xffffffffu, idxreg, 4 * j + quad);
        kv[j] = *(const uint4*)(g_Kh + (size_t)kidx[j] * EMB + h * HD + sub * 8);
    }

    #pragma unroll
    for (int j = 0; j < 4; j++) {
        float2 f0 = __half22float2(*(const __half2*)&kv[j].x);
        float2 f1 = __half22float2(*(const __half2*)&kv[j].y);
        float2 f2 = __half22float2(*(const __half2*)&kv[j].z);
        float2 f3 = __half22float2(*(const __half2*)&kv[j].w);
        float s;
        s  = qa.x * f0.x + qa.y * f0.y;
        s += qa.z * f1.x + qa.w * f1.y;
        s += qb.x * f2.x + qb.y * f2.y;
        s += qb.z * f3.x + qb.w * f3.y;
        s += __shfl_xor_sync(0xffffffffu, s, 4);
        s += __shfl_xor_sync(0xffffffffu, s, 2);
        s += __shfl_xor_sync(0xffffffffu, s, 1);
        if (sub == 0) rowp[kidx[j]] = s * 0.125f;   // 1/sqrt(64)
    }
}

// ---------------------------------------------------------------------------
extern "C" void kernel_launch(void* const* d_in, const int* in_sizes, int n_in,
                              void* d_out, int out_size)
{
    const float* emb = (const float*)d_in[0];
    const float* Wq  = (const float*)d_in[1];
    const float* bq  = (const float*)d_in[2];
    const float* Wk  = (const float*)d_in[3];
    const float* bk  = (const float*)d_in[4];
    const int*   idx = (const int*)d_in[5];
    float* out = (float*)d_out;

    __nv_bfloat16* x2;  cudaGetSymbolAddress((void**)&x2,  g_X2);
    __nv_bfloat16* w2q; cudaGetSymbolAddress((void**)&w2q, g_W2q);
    __nv_bfloat16* w2k; cudaGetSymbolAddress((void**)&w2k, g_W2k);

    split_convert_kernel<<<N_NODES, 256>>>(emb, x2, 0);
    split_convert_kernel<<<EMB, 256>>>(Wq, w2q, 1);
    split_convert_kernel<<<EMB, 256>>>(Wk, w2k, 1);

    dim3 ggrid(EMB / 64, N_NODES / 128, 2);   // 8 x 32 x 2
    proj_mma_kernel<<<ggrid, 256>>>(bq, bk);

    scatter_scores_kernel<<<N_HEADS * N_NODES, 256>>>(idx, out);
}

// round 7
// speedup vs baseline: 1.5916x; 1.1210x over previous
#include <cuda_runtime.h>
#include <cuda_fp16.h>
#include <cuda_bf16.h>
#include <cstdint>

#define N_NODES 4096
#define EMB     512
#define N_HEADS 8
#define KSP     128
#define HD      64
#define K_TOT   1536          // 3 * EMB (bf16 split: [hi|lo|hi] x [hi|hi|lo])

// Projected Q (fp32) and K (fp16). K row = 1KB; head slice = 128B, line-aligned.
__device__ float  g_Q [N_NODES * EMB];
__device__ __half g_Kh[N_NODES * EMB];

// bf16-split operands for the projection GEMMs
__device__ __align__(16) __nv_bfloat16 g_X2 [N_NODES * K_TOT];   // [hi | lo | hi]
__device__ __align__(16) __nv_bfloat16 g_W2q[EMB * K_TOT];       // [hi | hi | lo]
__device__ __align__(16) __nv_bfloat16 g_W2k[EMB * K_TOT];

// ════════════════ portable PTX helpers (valid at compute_103) ═══════════════
__device__ __forceinline__ uint32_t smem_u32_of(const void* p) {
    uint32_t a;
    asm("{ .reg .u64 t; cvta.to.shared.u64 t, %1; cvt.u32.u64 %0, t; }" : "=r"(a) : "l"(p));
    return a;
}
__device__ __forceinline__ void ldsm_x4(uint32_t* r, uint32_t addr) {
    asm volatile("ldmatrix.sync.aligned.m8n8.x4.shared.b16 {%0,%1,%2,%3}, [%4];"
                 : "=r"(r[0]), "=r"(r[1]), "=r"(r[2]), "=r"(r[3]) : "r"(addr));
}
__device__ __forceinline__ void mma_bf16(float* c, const uint32_t* a, const uint32_t* b) {
    asm volatile(
        "mma.sync.aligned.m16n8k16.row.col.f32.bf16.bf16.f32 "
        "{%0,%1,%2,%3}, {%4,%5,%6,%7}, {%8,%9}, {%0,%1,%2,%3};"
        : "+f"(c[0]), "+f"(c[1]), "+f"(c[2]), "+f"(c[3])
        : "r"(a[0]), "r"(a[1]), "r"(a[2]), "r"(a[3]), "r"(b[0]), "r"(b[1]));
}
__device__ __forceinline__ void cp16(uint32_t saddr, const void* gaddr) {
    asm volatile("cp.async.cg.shared.global [%0], [%1], 16;" :: "r"(saddr), "l"(gaddr));
}
#define CP_COMMIT() asm volatile("cp.async.commit_group;" ::: "memory")
#define CP_WAIT0()  asm volatile("cp.async.wait_group 0;" ::: "memory")

// ---------------------------------------------------------------------------
// bf16 split conversion. One block per source row (512 floats).
// mode 0 (activations): segs [hi | lo | hi]; mode 1 (weights): [hi | hi | lo]
// ---------------------------------------------------------------------------
__global__ void __launch_bounds__(256)
split_convert_kernel(const float* __restrict__ src, __nv_bfloat16* __restrict__ dst, int mode)
{
    const int row = blockIdx.x;
    const int c   = threadIdx.x * 2;
    float2 v = *(const float2*)(src + (size_t)row * EMB + c);
    __nv_bfloat16 h0 = __float2bfloat16_rn(v.x);
    __nv_bfloat16 h1 = __float2bfloat16_rn(v.y);
    __nv_bfloat16 l0 = __float2bfloat16_rn(v.x - __bfloat162float(h0));
    __nv_bfloat16 l1 = __float2bfloat16_rn(v.y - __bfloat162float(h1));
    __nv_bfloat162 H = {h0, h1}, L = {l0, l1};
    __nv_bfloat162* d0 = (__nv_bfloat162*)(dst + (size_t)row * K_TOT + c);
    d0[0] = H;
    if (mode == 0) { d0[256] = L; d0[512] = H; }
    else           { d0[256] = H; d0[512] = L; }
}

// ---------------------------------------------------------------------------
// HMMA projection GEMM v2: C[4096,512] = X2 @ W2^T, fp32 accumulate.
// CTA tile 128x128, BK=32, 8 warps in 4(M) x 2(N), warp tile 32x64
// -> MMA:ldsm ratio 32:6 per k16 (was 16:8). 2-stage cp.async.cg pipeline
// (no reg staging, L1-bypass on loads). grid=(512/128, 4096/128, 2).
// ---------------------------------------------------------------------------
#define BKG   32
#define NITER (K_TOT / BKG)     // 48
#define APAD  40                // 32 + 8 halves -> 80B row stride, ldsm conflict-free

__global__ void __launch_bounds__(256, 2)
proj_mma_kernel(const float* __restrict__ bq, const float* __restrict__ bk)
{
    __shared__ __align__(16) __nv_bfloat16 As[2][128][APAD];
    __shared__ __align__(16) __nv_bfloat16 Bs[2][128][APAD];

    const int t      = threadIdx.x;
    const int wid    = t >> 5;
    const int lane   = t & 31;
    const int warp_m = wid & 3;   // 4 warps over M (32 rows each)
    const int warp_n = wid >> 2;  // 2 warps over N (64 cols each)
    const int z      = blockIdx.z;
    const int rowBase = blockIdx.y * 128;
    const int colBase = blockIdx.x * 128;

    const __nv_bfloat16* Asrc = g_X2 + (size_t)rowBase * K_TOT;
    const __nv_bfloat16* Bsrc = (z ? g_W2k : g_W2q) + (size_t)colBase * K_TOT;

    // gmem<->smem chunk mapping: tile = 128 rows x 4 uint4-chunks; thread does
    // chunks t (row t/4) and t+256 (row t/4+64), col8 = t&3.
    const int cr = t >> 2, cc = t & 3;
    const __nv_bfloat16* gA0 = Asrc + (size_t)cr * K_TOT + cc * 8;
    const __nv_bfloat16* gA1 = Asrc + (size_t)(cr + 64) * K_TOT + cc * 8;
    const __nv_bfloat16* gB0 = Bsrc + (size_t)cr * K_TOT + cc * 8;
    const __nv_bfloat16* gB1 = Bsrc + (size_t)(cr + 64) * K_TOT + cc * 8;
    uint32_t sA0[2], sA1[2], sB0[2], sB1[2];
    #pragma unroll
    for (int buf = 0; buf < 2; buf++) {
        sA0[buf] = smem_u32_of(&As[buf][cr][cc * 8]);
        sA1[buf] = smem_u32_of(&As[buf][cr + 64][cc * 8]);
        sB0[buf] = smem_u32_of(&Bs[buf][cr][cc * 8]);
        sB1[buf] = smem_u32_of(&Bs[buf][cr + 64][cc * 8]);
    }

    float acc[2][8][4];
    #pragma unroll
    for (int mi = 0; mi < 2; mi++)
        #pragma unroll
        for (int ni = 0; ni < 8; ni++)
            #pragma unroll
            for (int e = 0; e < 4; e++) acc[mi][ni][e] = 0.0f;

    // ldmatrix base addresses (both buffers)
    const int arow = warp_m * 32 + (lane & 15);
    const int kcol = (lane >> 4) * 8;
    const int brow = warp_n * 64 + (lane & 15);
    uint32_t aAddr[2] = { smem_u32_of(&As[0][arow][kcol]), smem_u32_of(&As[1][arow][kcol]) };
    uint32_t bAddr[2] = { smem_u32_of(&Bs[0][brow][kcol]), smem_u32_of(&Bs[1][brow][kcol]) };

    // prologue: stage 0
    cp16(sA0[0], gA0); cp16(sA1[0], gA1);
    cp16(sB0[0], gB0); cp16(sB1[0], gB1);
    CP_COMMIT(); CP_WAIT0();
    __syncthreads();

    #pragma unroll 1
    for (int it = 0; it < NITER; ++it) {
        const int b = it & 1;
        if (it + 1 < NITER) {
            const int k1 = (it + 1) * BKG;
            const int nb = 1 - b;
            cp16(sA0[nb], gA0 + k1); cp16(sA1[nb], gA1 + k1);
            cp16(sB0[nb], gB0 + k1); cp16(sB1[nb], gB1 + k1);
            CP_COMMIT();
        }

        #pragma unroll
        for (int ks = 0; ks < 2; ks++) {
            uint32_t a[2][4];
            ldsm_x4(a[0], aAddr[b] + ks * 32);
            ldsm_x4(a[1], aAddr[b] + 16 * (APAD * 2) + ks * 32);
            uint32_t bf[8][2];
            #pragma unroll
            for (int nb4 = 0; nb4 < 4; nb4++) {
                uint32_t r[4];
                ldsm_x4(r, bAddr[b] + nb4 * 16 * (APAD * 2) + ks * 32);
                bf[2 * nb4 + 0][0] = r[0]; bf[2 * nb4 + 0][1] = r[2];
                bf[2 * nb4 + 1][0] = r[1]; bf[2 * nb4 + 1][1] = r[3];
            }
            #pragma unroll
            for (int mi = 0; mi < 2; mi++)
                #pragma unroll
                for (int ni = 0; ni < 8; ni++)
                    mma_bf16(acc[mi][ni], a[mi], bf[ni]);
        }

        CP_WAIT0();
        __syncthreads();
    }

    // Epilogue: d-frag m16n8 -> rows lane/4 (+8), cols (lane&3)*2; add bias.
    const float* bias = z ? bk : bq;
    const int mrow = rowBase + warp_m * 32 + (lane >> 2);
    #pragma unroll
    for (int mi = 0; mi < 2; mi++) {
        #pragma unroll
        for (int ni = 0; ni < 8; ni++) {
            const int gn = colBase + warp_n * 64 + ni * 8 + (lane & 3) * 2;
            const float2 bb = *(const float2*)(bias + gn);
            const int gm0 = mrow + mi * 16;
            if (z == 0) {
                float2 o0 = { acc[mi][ni][0] + bb.x, acc[mi][ni][1] + bb.y };
                float2 o1 = { acc[mi][ni][2] + bb.x, acc[mi][ni][3] + bb.y };
                *(float2*)(g_Q + (size_t)gm0 * EMB + gn)       = o0;
                *(float2*)(g_Q + (size_t)(gm0 + 8) * EMB + gn) = o1;
            } else {
                __half2 o0 = __floats2half2_rn(acc[mi][ni][0] + bb.x, acc[mi][ni][1] + bb.y);
                __half2 o1 = __floats2half2_rn(acc[mi][ni][2] + bb.x, acc[mi][ni][3] + bb.y);
                *(__half2*)(g_Kh + (size_t)gm0 * EMB + gn)       = o0;
                *(__half2*)(g_Kh + (size_t)(gm0 + 8) * EMB + gn) = o1;
            }
        }
    }
}

// ---------------------------------------------------------------------------
// Score + scatter (unchanged, 101.5us verified): fp16 key gather, one 128B
// line per key, direct GMEM zero-fill + scattered 4B stores.
// ---------------------------------------------------------------------------
__global__ void __launch_bounds__(256)
scatter_scores_kernel(const int* __restrict__ sidx, float* __restrict__ out)
{
    const int b = blockIdx.x;
    const int n = b & (N_NODES - 1);
    const int h = b >> 12;
    const int t = threadIdx.x;

    float* rowp = out + (size_t)b * N_NODES;

    float4 z = make_float4(0.f, 0.f, 0.f, 0.f);
    float4* op = (float4*)rowp;
    #pragma unroll
    for (int i = 0; i < 4; i++) op[t + i * 256] = z;

    const int warp = t >> 5;
    const int lane = t & 31;
    const int quad = lane >> 3;
    const int sub  = lane & 7;

    const int base = (((h << 12) | n) * KSP) + warp * 16;
    int idxreg = sidx[base + (lane & 15)];

    const float4* qp = (const float4*)(g_Q + (size_t)n * EMB + h * HD);
    float4 qa = qp[sub * 2];
    float4 qb = qp[sub * 2 + 1];

    __syncthreads();

    int  kidx[4];
    uint4 kv[4];
    #pragma unroll
    for (int j = 0; j < 4; j++) {
        kidx[j] = __shfl_sync(0xffffffffu, idxreg, 4 * j + quad);
        kv[j] = *(const uint4*)(g_Kh + (size_t)kidx[j] * EMB + h * HD + sub * 8);
    }

    #pragma unroll
    for (int j = 0; j < 4; j++) {
        float2 f0 = __half22float2(*(const __half2*)&kv[j].x);
        float2 f1 = __half22float2(*(const __half2*)&kv[j].y);
        float2 f2 = __half22float2(*(const __half2*)&kv[j].z);
        float2 f3 = __half22float2(*(const __half2*)&kv[j].w);
        float s;
        s  = qa.x * f0.x + qa.y * f0.y;
        s += qa.z * f1.x + qa.w * f1.y;
        s += qb.x * f2.x + qb.y * f2.y;
        s += qb.z * f3.x + qb.w * f3.y;
        s += __shfl_xor_sync(0xffffffffu, s, 4);
        s += __shfl_xor_sync(0xffffffffu, s, 2);
        s += __shfl_xor_sync(0xffffffffu, s, 1);
        if (sub == 0) rowp[kidx[j]] = s * 0.125f;   // 1/sqrt(64)
    }
}

// ---------------------------------------------------------------------------
extern "C" void kernel_launch(void* const* d_in, const int* in_sizes, int n_in,
                              void* d_out, int out_size)
{
    const float* emb = (const float*)d_in[0];
    const float* Wq  = (const float*)d_in[1];
    const float* bq  = (const float*)d_in[2];
    const float* Wk  = (const float*)d_in[3];
    const float* bk  = (const float*)d_in[4];
    const int*   idx = (const int*)d_in[5];
    float* out = (float*)d_out;

    __nv_bfloat16* x2;  cudaGetSymbolAddress((void**)&x2,  g_X2);
    __nv_bfloat16* w2q; cudaGetSymbolAddress((void**)&w2q, g_W2q);
    __nv_bfloat16* w2k; cudaGetSymbolAddress((void**)&w2k, g_W2k);

    split_convert_kernel<<<N_NODES, 256>>>(emb, x2, 0);
    split_convert_kernel<<<EMB, 256>>>(Wq, w2q, 1);
    split_convert_kernel<<<EMB, 256>>>(Wk, w2k, 1);

    dim3 ggrid(EMB / 128, N_NODES / 128, 2);   // 4 x 32 x 2
    proj_mma_kernel<<<ggrid, 256>>>(bq, bk);

    scatter_scores_kernel<<<N_HEADS * N_NODES, 256>>>(idx, out);
}

// round 8
// speedup vs baseline: 1.5956x; 1.0025x over previous
#include <cuda_runtime.h>
#include <cuda_fp16.h>
#include <cuda_bf16.h>
#include <cstdint>

#define N_NODES 4096
#define EMB     512
#define N_HEADS 8
#define KSP     128
#define HD      64
#define K_TOT   1536          // 3 * EMB (bf16 split: [hi|lo|hi] x [hi|hi|lo])

// Projected Q (fp32) and K (fp16). K row = 1KB; head slice = 128B, line-aligned.
__device__ float  g_Q [N_NODES * EMB];
__device__ __half g_Kh[N_NODES * EMB];

// bf16-split operands for the projection GEMMs
__device__ __align__(16) __nv_bfloat16 g_X2 [N_NODES * K_TOT];   // [hi | lo | hi]
__device__ __align__(16) __nv_bfloat16 g_W2q[EMB * K_TOT];       // [hi | hi | lo]
__device__ __align__(16) __nv_bfloat16 g_W2k[EMB * K_TOT];

// ════════════════ portable PTX helpers (valid at compute_103) ═══════════════
__device__ __forceinline__ uint32_t smem_u32_of(const void* p) {
    uint32_t a;
    asm("{ .reg .u64 t; cvta.to.shared.u64 t, %1; cvt.u32.u64 %0, t; }" : "=r"(a) : "l"(p));
    return a;
}
__device__ __forceinline__ void ldsm_x4(uint32_t* r, uint32_t addr) {
    asm volatile("ldmatrix.sync.aligned.m8n8.x4.shared.b16 {%0,%1,%2,%3}, [%4];"
                 : "=r"(r[0]), "=r"(r[1]), "=r"(r[2]), "=r"(r[3]) : "r"(addr));
}
__device__ __forceinline__ void mma_bf16(float* c, const uint32_t* a, const uint32_t* b) {
    asm volatile(
        "mma.sync.aligned.m16n8k16.row.col.f32.bf16.bf16.f32 "
        "{%0,%1,%2,%3}, {%4,%5,%6,%7}, {%8,%9}, {%0,%1,%2,%3};"
        : "+f"(c[0]), "+f"(c[1]), "+f"(c[2]), "+f"(c[3])
        : "r"(a[0]), "r"(a[1]), "r"(a[2]), "r"(a[3]), "r"(b[0]), "r"(b[1]));
}
__device__ __forceinline__ void cp16(uint32_t saddr, const void* gaddr) {
    asm volatile("cp.async.cg.shared.global [%0], [%1], 16;" :: "r"(saddr), "l"(gaddr));
}
#define CP_COMMIT() asm volatile("cp.async.commit_group;" ::: "memory")
#define CP_WAIT0()  asm volatile("cp.async.wait_group 0;" ::: "memory")
#define CP_WAIT1()  asm volatile("cp.async.wait_group 1;" ::: "memory")

// ---------------------------------------------------------------------------
// Fused bf16 split conversion (one launch for X, Wq, Wk).
// rows [0,4096) -> X2 mode0 [hi|lo|hi]; [4096,4608) -> W2q; [4608,5120) -> W2k
// mode1 [hi|hi|lo].
// ---------------------------------------------------------------------------
__global__ void __launch_bounds__(256)
split_convert_all(const float* __restrict__ X,
                  const float* __restrict__ Wq, const float* __restrict__ Wk)
{
    const int r = blockIdx.x;
    const float* src;
    __nv_bfloat16* dst;
    int mode;
    if (r < N_NODES)            { src = X  + (size_t)r * EMB;              dst = g_X2  + (size_t)r * K_TOT;              mode = 0; }
    else if (r < N_NODES + EMB) { src = Wq + (size_t)(r - N_NODES) * EMB;  dst = g_W2q + (size_t)(r - N_NODES) * K_TOT;  mode = 1; }
    else                        { src = Wk + (size_t)(r - N_NODES - EMB) * EMB; dst = g_W2k + (size_t)(r - N_NODES - EMB) * K_TOT; mode = 1; }

    const int c = threadIdx.x * 2;
    float2 v = *(const float2*)(src + c);
    __nv_bfloat16 h0 = __float2bfloat16_rn(v.x);
    __nv_bfloat16 h1 = __float2bfloat16_rn(v.y);
    __nv_bfloat16 l0 = __float2bfloat16_rn(v.x - __bfloat162float(h0));
    __nv_bfloat16 l1 = __float2bfloat16_rn(v.y - __bfloat162float(h1));
    __nv_bfloat162 H = {h0, h1}, L = {l0, l1};
    __nv_bfloat162* d0 = (__nv_bfloat162*)(dst + c);
    d0[0] = H;
    if (mode == 0) { d0[256] = L; d0[512] = H; }
    else           { d0[256] = H; d0[512] = L; }
}

// ---------------------------------------------------------------------------
// HMMA projection GEMM v3: 3-stage cp.async pipeline (wait_group 1) so each
// load has ~2 iterations in flight; dynamic smem (3 x 20KB stages).
// CTA 128x128, BK=32, 8 warps 4(M)x2(N), warp tile 32x64.
// ---------------------------------------------------------------------------
#define BKG    32
#define NITER  (K_TOT / BKG)     // 48
#define APAD   40                // 80B row stride, ldsm conflict-free
#define AST_B  (128 * APAD * 2)  // 10240B per operand per stage
#define STAGE  (2 * AST_B)       // 20480B
#define SMEMSZ (3 * STAGE)       // 61440B

__global__ void __launch_bounds__(256, 2)
proj_mma_kernel(const float* __restrict__ bq, const float* __restrict__ bk)
{
    extern __shared__ __align__(16) char smem[];
    const uint32_t sbase = smem_u32_of(smem);

    const int t      = threadIdx.x;
    const int wid    = t >> 5;
    const int lane   = t & 31;
    const int warp_m = wid & 3;   // 4 warps over M (32 rows each)
    const int warp_n = wid >> 2;  // 2 warps over N (64 cols each)
    const int z      = blockIdx.z;
    const int rowBase = blockIdx.y * 128;
    const int colBase = blockIdx.x * 128;

    const __nv_bfloat16* Asrc = g_X2 + (size_t)rowBase * K_TOT;
    const __nv_bfloat16* Bsrc = (z ? g_W2k : g_W2q) + (size_t)colBase * K_TOT;

    // gmem<->smem chunk mapping: 128 rows x 4 uint4-chunks per operand;
    // thread handles rows cr and cr+64 at chunk cc.
    const int cr = t >> 2, cc = t & 3;
    const __nv_bfloat16* gA0 = Asrc + (size_t)cr * K_TOT + cc * 8;
    const __nv_bfloat16* gA1 = Asrc + (size_t)(cr + 64) * K_TOT + cc * 8;
    const __nv_bfloat16* gB0 = Bsrc + (size_t)cr * K_TOT + cc * 8;
    const __nv_bfloat16* gB1 = Bsrc + (size_t)(cr + 64) * K_TOT + cc * 8;

    uint32_t sA0[3], sA1[3], sB0[3], sB1[3], aAd[3], bAd[3];
    {
        const int arow = warp_m * 32 + (lane & 15);
        const int kcol = (lane >> 4) * 8;
        const int brow = warp_n * 64 + (lane & 15);
        #pragma unroll
        for (int s = 0; s < 3; s++) {
            const uint32_t a0 = sbase + s * STAGE;
            const uint32_t b0 = a0 + AST_B;
            sA0[s] = a0 + (cr * APAD + cc * 8) * 2;
            sA1[s] = a0 + ((cr + 64) * APAD + cc * 8) * 2;
            sB0[s] = b0 + (cr * APAD + cc * 8) * 2;
            sB1[s] = b0 + ((cr + 64) * APAD + cc * 8) * 2;
            aAd[s] = a0 + (arow * APAD + kcol) * 2;
            bAd[s] = b0 + (brow * APAD + kcol) * 2;
        }
    }

    float acc[2][8][4];
    #pragma unroll
    for (int mi = 0; mi < 2; mi++)
        #pragma unroll
        for (int ni = 0; ni < 8; ni++)
            #pragma unroll
            for (int e = 0; e < 4; e++) acc[mi][ni][e] = 0.0f;

    // prologue: stages 0 and 1
    #pragma unroll
    for (int s = 0; s < 2; s++) {
        const int k0 = s * BKG;
        cp16(sA0[s], gA0 + k0); cp16(sA1[s], gA1 + k0);
        cp16(sB0[s], gB0 + k0); cp16(sB1[s], gB1 + k0);
        CP_COMMIT();
    }

    #pragma unroll 1
    for (int it = 0; it < NITER; ++it) {
        const int b = it % 3;
        // arrival of stage it (leave stage it+1 in flight); last iter drains all
        if (it + 1 < NITER) CP_WAIT1(); else CP_WAIT0();
        __syncthreads();          // cross-thread visibility + stage (it+2)%3 free

        if (it + 2 < NITER) {
            const int k2 = (it + 2) * BKG;
            const int nb = (it + 2) % 3;
            cp16(sA0[nb], gA0 + k2); cp16(sA1[nb], gA1 + k2);
            cp16(sB0[nb], gB0 + k2); cp16(sB1[nb], gB1 + k2);
            CP_COMMIT();
        }

        #pragma unroll
        for (int ks = 0; ks < 2; ks++) {
            uint32_t a[2][4];
            ldsm_x4(a[0], aAd[b] + ks * 32);
            ldsm_x4(a[1], aAd[b] + 16 * (APAD * 2) + ks * 32);
            uint32_t bf[8][2];
            #pragma unroll
            for (int nb4 = 0; nb4 < 4; nb4++) {
                uint32_t r[4];
                ldsm_x4(r, bAd[b] + nb4 * 16 * (APAD * 2) + ks * 32);
                bf[2 * nb4 + 0][0] = r[0]; bf[2 * nb4 + 0][1] = r[2];
                bf[2 * nb4 + 1][0] = r[1]; bf[2 * nb4 + 1][1] = r[3];
            }
            #pragma unroll
            for (int mi = 0; mi < 2; mi++)
                #pragma unroll
                for (int ni = 0; ni < 8; ni++)
                    mma_bf16(acc[mi][ni], a[mi], bf[ni]);
        }
    }

    // Epilogue: d-frag m16n8 -> rows lane/4 (+8), cols (lane&3)*2; add bias.
    const float* bias = z ? bk : bq;
    const int mrow = rowBase + warp_m * 32 + (lane >> 2);
    #pragma unroll
    for (int mi = 0; mi < 2; mi++) {
        #pragma unroll
        for (int ni = 0; ni < 8; ni++) {
            const int gn = colBase + warp_n * 64 + ni * 8 + (lane & 3) * 2;
            const float2 bb = *(const float2*)(bias + gn);
            const int gm0 = mrow + mi * 16;
            if (z == 0) {
                float2 o0 = { acc[mi][ni][0] + bb.x, acc[mi][ni][1] + bb.y };
                float2 o1 = { acc[mi][ni][2] + bb.x, acc[mi][ni][3] + bb.y };
                *(float2*)(g_Q + (size_t)gm0 * EMB + gn)       = o0;
                *(float2*)(g_Q + (size_t)(gm0 + 8) * EMB + gn) = o1;
            } else {
                __half2 o0 = __floats2half2_rn(acc[mi][ni][0] + bb.x, acc[mi][ni][1] + bb.y);
                __half2 o1 = __floats2half2_rn(acc[mi][ni][2] + bb.x, acc[mi][ni][3] + bb.y);
                *(__half2*)(g_Kh + (size_t)gm0 * EMB + gn)       = o0;
                *(__half2*)(g_Kh + (size_t)(gm0 + 8) * EMB + gn) = o1;
            }
        }
    }
}

// ---------------------------------------------------------------------------
// Score + scatter (unchanged, 101.5us verified): fp16 key gather, one 128B
// line per key, direct GMEM zero-fill + scattered 4B stores.
// ---------------------------------------------------------------------------
__global__ void __launch_bounds__(256)
scatter_scores_kernel(const int* __restrict__ sidx, float* __restrict__ out)
{
    const int b = blockIdx.x;
    const int n = b & (N_NODES - 1);
    const int h = b >> 12;
    const int t = threadIdx.x;

    float* rowp = out + (size_t)b * N_NODES;

    float4 z = make_float4(0.f, 0.f, 0.f, 0.f);
    float4* op = (float4*)rowp;
    #pragma unroll
    for (int i = 0; i < 4; i++) op[t + i * 256] = z;

    const int warp = t >> 5;
    const int lane = t & 31;
    const int quad = lane >> 3;
    const int sub  = lane & 7;

    const int base = (((h << 12) | n) * KSP) + warp * 16;
    int idxreg = sidx[base + (lane & 15)];

    const float4* qp = (const float4*)(g_Q + (size_t)n * EMB + h * HD);
    float4 qa = qp[sub * 2];
    float4 qb = qp[sub * 2 + 1];

    __syncthreads();

    int  kidx[4];
    uint4 kv[4];
    #pragma unroll
    for (int j = 0; j < 4; j++) {
        kidx[j] = __shfl_sync(0xffffffffu, idxreg, 4 * j + quad);
        kv[j] = *(const uint4*)(g_Kh + (size_t)kidx[j] * EMB + h * HD + sub * 8);
    }

    #pragma unroll
    for (int j = 0; j < 4; j++) {
        float2 f0 = __half22float2(*(const __half2*)&kv[j].x);
        float2 f1 = __half22float2(*(const __half2*)&kv[j].y);
        float2 f2 = __half22float2(*(const __half2*)&kv[j].z);
        float2 f3 = __half22float2(*(const __half2*)&kv[j].w);
        float s;
        s  = qa.x * f0.x + qa.y * f0.y;
        s += qa.z * f1.x + qa.w * f1.y;
        s += qb.x * f2.x + qb.y * f2.y;
        s += qb.z * f3.x + qb.w * f3.y;
        s += __shfl_xor_sync(0xffffffffu, s, 4);
        s += __shfl_xor_sync(0xffffffffu, s, 2);
        s += __shfl_xor_sync(0xffffffffu, s, 1);
        if (sub == 0) rowp[kidx[j]] = s * 0.125f;   // 1/sqrt(64)
    }
}

// ---------------------------------------------------------------------------
extern "C" void kernel_launch(void* const* d_in, const int* in_sizes, int n_in,
                              void* d_out, int out_size)
{
    const float* emb = (const float*)d_in[0];
    const float* Wq  = (const float*)d_in[1];
    const float* bq  = (const float*)d_in[2];
    const float* Wk  = (const float*)d_in[3];
    const float* bk  = (const float*)d_in[4];
    const int*   idx = (const int*)d_in[5];
    float* out = (float*)d_out;

    static int smem_set = 0;
    if (!smem_set) {
        cudaFuncSetAttribute(proj_mma_kernel,
                             cudaFuncAttributeMaxDynamicSharedMemorySize, SMEMSZ);
        smem_set = 1;
    }

    split_convert_all<<<N_NODES + 2 * EMB, 256>>>(emb, Wq, Wk);

    dim3 ggrid(EMB / 128, N_NODES / 128, 2);   // 4 x 32 x 2
    proj_mma_kernel<<<ggrid, 256, SMEMSZ>>>(bq, bk);

    scatter_scores_kernel<<<N_HEADS * N_NODES, 256>>>(idx, out);
}